// round 1
// baseline (speedup 1.0000x reference)
#include <cuda_runtime.h>
#include <math.h>
#include <stdint.h>

#define BSG   8          // B*S graphs
#define L     1024       // nodes per graph
#define C     128        // feature dim
#define HIMG  256
#define WIMG  256
#define NEG   0.2f
#define LNEPS 1e-5f

// ---------------- scratch (static device globals; no allocs) ----------------
__device__ uint32_t g_adj[BSG][L][L / 32];        // 1 MB adjacency bitmask
__device__ float    g_wf[BSG * L * C];            // 4 MB  Wf for current layer
__device__ float    g_h1[BSG * L * C];            // 4 MB  layer-1 output
__device__ float    g_esrc[BSG * L * 4];          // e_src (max 4 heads)
__device__ float    g_edst[BSG * L * 4];          // e_dst

// ---------------- adjacency ----------------
__global__ void k_adj_init() {
    int idx = blockIdx.x * blockDim.x + threadIdx.x;   // over BSG*L*32 words
    if (idx >= BSG * L * 32) return;
    int w = idx & 31;
    int i = (idx >> 5) & (L - 1);
    uint32_t v = (w == (i >> 5)) ? (1u << (i & 31)) : 0u;  // self-loop diagonal
    ((uint32_t*)g_adj)[idx] = v;
}

__global__ void k_adj_build(const int* __restrict__ img) {
    int idx = blockIdx.x * blockDim.x + threadIdx.x;   // over BSG*H*W pixels
    if (idx >= BSG * HIMG * WIMG) return;
    int x  = idx & (WIMG - 1);
    int y  = (idx >> 8) & (HIMG - 1);
    int gg = idx >> 16;
    const int* base = img + gg * HIMG * WIMG;
    int p = base[y * WIMG + x];

    auto edge = [&](int a, int b) {
        if (a > 0 && b > 0 && a != b) {
            int ai = a - 1, bi = b - 1;
            atomicOr(&g_adj[gg][ai][bi >> 5], 1u << (bi & 31));
            atomicOr(&g_adj[gg][bi][ai >> 5], 1u << (ai & 31));
        }
    };
    if (x + 1 < WIMG) edge(p, base[y * WIMG + x + 1]);            // horizontal
    if (y + 1 < HIMG) {
        edge(p, base[(y + 1) * WIMG + x]);                        // vertical
        if (x + 1 < WIMG) edge(p, base[(y + 1) * WIMG + x + 1]);  // diag backslash
        if (x > 0)        edge(p, base[(y + 1) * WIMG + x - 1]);  // diag slash
    }
}

// ---------------- NT GEMM: out[g][r][o] = sum_k in[g][r][k] * W[o][k] ----------------
// 256 threads, 32 rows x 128 cols per block, 4x4 microtile per thread.
__global__ void __launch_bounds__(256) k_gemm_nt(const float* __restrict__ in,
                                                 const float* __restrict__ W) {
    __shared__ float4 xs[32][9];    // [r][kq] padded (conflict-free)
    __shared__ float4 ws[128][9];   // [o][kq] padded
    int tid = threadIdx.x;
    int gg  = blockIdx.x >> 5;
    int r0  = (blockIdx.x & 31) * 32;
    const float* src = in ? (in + gg * L * C) : (g_h1 + gg * L * C);
    const float4* in4 = (const float4*)src;
    const float4* W4  = (const float4*)W;
    int tx = tid & 31, ty = tid >> 5;
    float acc[4][4] = {};

    for (int k0 = 0; k0 < 32; k0 += 8) {           // k0 in float4 units
        {   // load X tile: 32 rows x 8 f4
            int r = tid >> 3, kq = tid & 7;
            xs[r][kq] = in4[(r0 + r) * 32 + k0 + kq];
        }
        #pragma unroll
        for (int it = 0; it < 4; it++) {           // load W tile: 128 x 8 f4
            int idx = tid + it * 256;
            int o = idx >> 3, kq = idx & 7;
            ws[o][kq] = W4[o * 32 + k0 + kq];
        }
        __syncthreads();
        #pragma unroll
        for (int kq = 0; kq < 8; kq++) {
            float4 xv[4], wv[4];
            #pragma unroll
            for (int rr = 0; rr < 4; rr++) xv[rr] = xs[ty * 4 + rr][kq];
            #pragma unroll
            for (int cc = 0; cc < 4; cc++) wv[cc] = ws[tx + 32 * cc][kq];
            #pragma unroll
            for (int rr = 0; rr < 4; rr++)
                #pragma unroll
                for (int cc = 0; cc < 4; cc++)
                    acc[rr][cc] += xv[rr].x * wv[cc].x + xv[rr].y * wv[cc].y
                                 + xv[rr].z * wv[cc].z + xv[rr].w * wv[cc].w;
        }
        __syncthreads();
    }
    float* ob = g_wf + gg * L * C;
    #pragma unroll
    for (int rr = 0; rr < 4; rr++)
        #pragma unroll
        for (int cc = 0; cc < 4; cc++)
            ob[(r0 + ty * 4 + rr) * C + tx + 32 * cc] = acc[rr][cc];
}

// ---------------- per-row attention coefficients: e_src/e_dst ----------------
template<int HEADS>
__global__ void __launch_bounds__(256) k_attprep(const float* __restrict__ asrc,
                                                 const float* __restrict__ adst) {
    int warp = (blockIdx.x * blockDim.x + threadIdx.x) >> 5;
    int lane = threadIdx.x & 31;
    if (warp >= BSG * L) return;
    float4 v  = ((const float4*)(g_wf + warp * C))[lane];
    float4 sa = ((const float4*)asrc)[lane];
    float4 da = ((const float4*)adst)[lane];
    float ps = v.x * sa.x + v.y * sa.y + v.z * sa.z + v.w * sa.w;
    float pd = v.x * da.x + v.y * da.y + v.z * da.z + v.w * da.w;
    const int G = 32 / HEADS;   // lanes per head
    #pragma unroll
    for (int off = G >> 1; off > 0; off >>= 1) {
        ps += __shfl_xor_sync(0xffffffffu, ps, off);
        pd += __shfl_xor_sync(0xffffffffu, pd, off);
    }
    if ((lane & (G - 1)) == 0) {
        int h = lane / G;
        g_esrc[warp * HEADS + h] = ps;
        g_edst[warp * HEADS + h] = pd;
    }
}

// ---------------- fused masked-softmax attention ----------------
// MODE 0: output = ELU(h), write g_h1.     MODE 1: residual + LayerNorm, write out.
template<int HEADS, int MODE>
__global__ void __launch_bounds__(128) k_attn(const float* __restrict__ feats,
                                              const float* __restrict__ gamma,
                                              const float* __restrict__ beta,
                                              float* __restrict__ out) {
    constexpr int TI = 16, JC = 32;
    __shared__ float t_sh[L * HEADS];                       // e_dst for all j
    __shared__ float4 wf_sh[JC][32];                        // Wf j-chunk
    __shared__ __align__(16) float alpha_sh[JC][HEADS][TI]; // attention weights
    __shared__ uint32_t adj_sh[TI][32];
    __shared__ float s_sh[TI * HEADS], m_sh[TI * HEADS], rl_sh[TI * HEADS];
    __shared__ float pm[128], pl[128];

    int tid = threadIdx.x;
    int gg  = blockIdx.x >> 6;            // 64 row-tiles per graph
    int i0  = (blockIdx.x & 63) * TI;

    for (int idx = tid; idx < L * HEADS; idx += 128)
        t_sh[idx] = g_edst[gg * L * HEADS + idx];
    for (int idx = tid; idx < TI * 32; idx += 128)
        adj_sh[idx >> 5][idx & 31] = g_adj[gg][i0 + (idx >> 5)][idx & 31];
    if (tid < TI * HEADS)
        s_sh[tid] = g_esrc[gg * L * HEADS + i0 * HEADS + tid];
    __syncthreads();

    // ---- phase B: per-(row,head) masked softmax stats (online max/sum) ----
    constexpr int P = TI * HEADS;         // 64 (L1) or 16 (L2)
    constexpr int TPER = 128 / P;         // 2 or 8
    {
        int pair = tid / TPER, sub = tid % TPER;
        int r = pair / HEADS, h = pair % HEADS;
        float s = s_sh[pair];
        float m = -1e30f, l = 0.f;
        for (int j = sub; j < L; j += TPER) {
            if (adj_sh[r][j >> 5] & (1u << (j & 31))) {
                float e = s + t_sh[j * HEADS + h];
                e = e >= 0.f ? e : NEG * e;
                if (e > m) { l *= expf(m - e); m = e; }
                l += expf(e - m);
            }
        }
        pm[tid] = m; pl[tid] = l;
    }
    __syncthreads();
    if (tid < P) {
        float M = -1e30f, LL = 0.f;
        #pragma unroll
        for (int k = 0; k < TPER; k++) M = fmaxf(M, pm[tid * TPER + k]);
        #pragma unroll
        for (int k = 0; k < TPER; k++) LL += pl[tid * TPER + k] * expf(pm[tid * TPER + k] - M);
        m_sh[tid]  = M;
        rl_sh[tid] = 1.f / LL;    // diagonal guarantees LL > 0
    }
    __syncthreads();

    // ---- phase C: dense chunked accumulation acc += alpha * Wf ----
    int dcol = tid & 31, ig = tid >> 5;
    constexpr int DH = 32 / HEADS;        // dcols per head
    int myh = dcol / DH;
    float4 acc[4];
    #pragma unroll
    for (int rr = 0; rr < 4; rr++) acc[rr] = make_float4(0.f, 0.f, 0.f, 0.f);
    const float4* wfg = (const float4*)(g_wf + gg * L * C);

    for (int jb = 0; jb < L; jb += JC) {
        #pragma unroll
        for (int it = 0; it < 8; it++) {                 // Wf tile: 32 j x 32 f4
            int idx = tid + it * 128;
            wf_sh[idx >> 5][idx & 31] = wfg[jb * 32 + idx];
        }
        for (int idx = tid; idx < JC * HEADS * TI; idx += 128) {
            int jj  = idx / (HEADS * TI);
            int rem = idx % (HEADS * TI);
            int h = rem / TI, r = rem % TI;
            int j = jb + jj;
            float a = 0.f;
            if (adj_sh[r][j >> 5] & (1u << (j & 31))) {
                float e = s_sh[r * HEADS + h] + t_sh[j * HEADS + h];
                e = e >= 0.f ? e : NEG * e;
                a = expf(e - m_sh[r * HEADS + h]) * rl_sh[r * HEADS + h];
            }
            alpha_sh[jj][h][r] = a;
        }
        __syncthreads();
        #pragma unroll 4
        for (int jj = 0; jj < JC; jj++) {
            float4 w = wf_sh[jj][dcol];
            float4 a = *reinterpret_cast<const float4*>(&alpha_sh[jj][myh][ig * 4]);
            acc[0].x += a.x * w.x; acc[0].y += a.x * w.y; acc[0].z += a.x * w.z; acc[0].w += a.x * w.w;
            acc[1].x += a.y * w.x; acc[1].y += a.y * w.y; acc[1].z += a.y * w.z; acc[1].w += a.y * w.w;
            acc[2].x += a.z * w.x; acc[2].y += a.z * w.y; acc[2].z += a.z * w.z; acc[2].w += a.z * w.w;
            acc[3].x += a.w * w.x; acc[3].y += a.w * w.y; acc[3].z += a.w * w.z; acc[3].w += a.w * w.w;
        }
        __syncthreads();
    }

    int rowbase = i0 + ig * 4;
    if (MODE == 0) {
        float* hb = g_h1 + gg * L * C;
        #pragma unroll
        for (int rr = 0; rr < 4; rr++) {
            float4 v = acc[rr];
            v.x = v.x > 0.f ? v.x : expm1f(v.x);
            v.y = v.y > 0.f ? v.y : expm1f(v.y);
            v.z = v.z > 0.f ? v.z : expm1f(v.z);
            v.w = v.w > 0.f ? v.w : expm1f(v.w);
            ((float4*)(hb + (rowbase + rr) * C))[dcol] = v;
        }
    } else {
        const float4* fg = (const float4*)(feats + gg * L * C);
        float4 gm = ((const float4*)gamma)[dcol];
        float4 bt = ((const float4*)beta)[dcol];
        float4* og = (float4*)(out + gg * L * C);
        #pragma unroll
        for (int rr = 0; rr < 4; rr++) {
            float4 y = fg[(rowbase + rr) * 32 + dcol];
            y.x += acc[rr].x; y.y += acc[rr].y; y.z += acc[rr].z; y.w += acc[rr].w;
            float sm = y.x + y.y + y.z + y.w;
            float sq = y.x * y.x + y.y * y.y + y.z * y.z + y.w * y.w;
            #pragma unroll
            for (int off = 16; off > 0; off >>= 1) {
                sm += __shfl_xor_sync(0xffffffffu, sm, off);
                sq += __shfl_xor_sync(0xffffffffu, sq, off);
            }
            float mean = sm * (1.f / 128.f);
            float var  = sq * (1.f / 128.f) - mean * mean;
            float inv  = rsqrtf(var + LNEPS);
            float4 o;
            o.x = (y.x - mean) * inv * gm.x + bt.x;
            o.y = (y.y - mean) * inv * gm.y + bt.y;
            o.z = (y.z - mean) * inv * gm.z + bt.z;
            o.w = (y.w - mean) * inv * gm.w + bt.w;
            og[(rowbase + rr) * 32 + dcol] = o;
        }
    }
}

// ---------------- launch ----------------
extern "C" void kernel_launch(void* const* d_in, const int* in_sizes, int n_in,
                              void* d_out, int out_size) {
    const float* seg_feats = (const float*)d_in[0];
    const int*   seg_img   = (const int*)d_in[1];
    // d_in[2] seg_nums unused by the reference forward
    const float* W1    = (const float*)d_in[3];
    const float* asrc1 = (const float*)d_in[4];
    const float* adst1 = (const float*)d_in[5];
    const float* W2    = (const float*)d_in[6];
    const float* asrc2 = (const float*)d_in[7];
    const float* adst2 = (const float*)d_in[8];
    const float* gamma = (const float*)d_in[9];
    const float* beta  = (const float*)d_in[10];
    float* out = (float*)d_out;

    k_adj_init <<<(BSG * L * 32 + 255) / 256, 256>>>();
    k_adj_build<<<(BSG * HIMG * WIMG + 255) / 256, 256>>>(seg_img);

    // layer 1
    k_gemm_nt  <<<BSG * 32, 256>>>(seg_feats, W1);
    k_attprep<4><<<(BSG * L * 32) / 256, 256>>>(asrc1, adst1);
    k_attn<4, 0><<<BSG * 64, 128>>>(nullptr, nullptr, nullptr, nullptr);

    // layer 2 (input = g_h1 via in==nullptr)
    k_gemm_nt  <<<BSG * 32, 256>>>(nullptr, W2);
    k_attprep<1><<<(BSG * L * 32) / 256, 256>>>(asrc2, adst2);
    k_attn<1, 1><<<BSG * 64, 128>>>(seg_feats, gamma, beta, out);
}

// round 2
// speedup vs baseline: 1.4775x; 1.4775x over previous
#include <cuda_runtime.h>
#include <math.h>
#include <stdint.h>

#define BSG   8          // B*S graphs
#define L     1024       // nodes per graph
#define C     128        // feature dim
#define HIMG  256
#define WIMG  256
#define NEG   0.2f
#define LNEPS 1e-5f

// ---------------- scratch (static device globals; no allocs) ----------------
__device__ uint32_t g_adj[BSG][L][L / 32];        // 1 MB adjacency bitmask
__device__ float    g_wf[BSG * L * C];            // Wf for current layer
__device__ float    g_h1[BSG * L * C];            // layer-1 output
__device__ float    g_esrc[BSG * L * 4];
__device__ float    g_edst[BSG * L * 4];

// ---------------- packed f32x2 helpers (FFMA2) ----------------
__device__ __forceinline__ unsigned long long dup2(float a) {
    unsigned long long r;
    asm("mov.b64 %0, {%1, %1};" : "=l"(r) : "f"(a));
    return r;
}
__device__ __forceinline__ void ffma2(unsigned long long& d,
                                      unsigned long long a, unsigned long long b) {
    asm("fma.rn.f32x2 %0, %1, %2, %0;" : "+l"(d) : "l"(a), "l"(b));
}
__device__ __forceinline__ float2 unpk(unsigned long long v) {
    float lo, hi;
    asm("mov.b64 {%0, %1}, %2;" : "=f"(lo), "=f"(hi) : "l"(v));
    return make_float2(lo, hi);
}

// ---------------- adjacency ----------------
__global__ void k_adj_init() {
    int idx = blockIdx.x * blockDim.x + threadIdx.x;   // BSG*L*32 words
    if (idx >= BSG * L * 32) return;
    int w = idx & 31;
    int i = (idx >> 5) & (L - 1);
    ((uint32_t*)g_adj)[idx] = (w == (i >> 5)) ? (1u << (i & 31)) : 0u;
}

__global__ void k_adj_build(const int* __restrict__ img) {
    int idx = blockIdx.x * blockDim.x + threadIdx.x;   // BSG*H*W pixels
    if (idx >= BSG * HIMG * WIMG) return;
    int x  = idx & (WIMG - 1);
    int y  = (idx >> 8) & (HIMG - 1);
    int gg = idx >> 16;
    const int* base = img + gg * HIMG * WIMG;
    int p = base[y * WIMG + x];

    auto edge = [&](int a, int b) {
        if (a > 0 && b > 0 && a != b) {
            int ai = a - 1, bi = b - 1;
            atomicOr(&g_adj[gg][ai][bi >> 5], 1u << (bi & 31));
            atomicOr(&g_adj[gg][bi][ai >> 5], 1u << (ai & 31));
        }
    };
    if (x + 1 < WIMG) edge(p, base[y * WIMG + x + 1]);
    if (y + 1 < HIMG) {
        edge(p, base[(y + 1) * WIMG + x]);
        if (x + 1 < WIMG) edge(p, base[(y + 1) * WIMG + x + 1]);
        if (x > 0)        edge(p, base[(y + 1) * WIMG + x - 1]);
    }
}

// ---------------- NT GEMM + fused e_src/e_dst epilogue ----------------
// out[g][r][o] = sum_k in[g][r][k]*W[o][k]; then per-(row,head) dots with a_src/a_dst.
template<int HEADS>
__global__ void __launch_bounds__(256) k_gemm_nt(const float* __restrict__ in,
                                                 const float* __restrict__ W,
                                                 const float* __restrict__ asrc,
                                                 const float* __restrict__ adst) {
    __shared__ float4 xs[32][9];
    __shared__ float4 ws[128][9];
    int tid = threadIdx.x;
    int gg  = blockIdx.x >> 5;
    int r0  = (blockIdx.x & 31) * 32;
    const float* src = in ? (in + gg * L * C) : (g_h1 + gg * L * C);
    const float4* in4 = (const float4*)src;
    const float4* W4  = (const float4*)W;
    int tx = tid & 31, ty = tid >> 5;
    float acc[4][4] = {};

    for (int k0 = 0; k0 < 32; k0 += 8) {
        {
            int r = tid >> 3, kq = tid & 7;
            xs[r][kq] = in4[(r0 + r) * 32 + k0 + kq];
        }
        #pragma unroll
        for (int it = 0; it < 4; it++) {
            int idx = tid + it * 256;
            int o = idx >> 3, kq = idx & 7;
            ws[o][kq] = W4[o * 32 + k0 + kq];
        }
        __syncthreads();
        #pragma unroll
        for (int kq = 0; kq < 8; kq++) {
            float4 xv[4], wv[4];
            #pragma unroll
            for (int rr = 0; rr < 4; rr++) xv[rr] = xs[ty * 4 + rr][kq];
            #pragma unroll
            for (int cc = 0; cc < 4; cc++) wv[cc] = ws[tx + 32 * cc][kq];
            #pragma unroll
            for (int rr = 0; rr < 4; rr++)
                #pragma unroll
                for (int cc = 0; cc < 4; cc++)
                    acc[rr][cc] += xv[rr].x * wv[cc].x + xv[rr].y * wv[cc].y
                                 + xv[rr].z * wv[cc].z + xv[rr].w * wv[cc].w;
        }
        __syncthreads();
    }
    float* ob = g_wf + gg * L * C;
    #pragma unroll
    for (int rr = 0; rr < 4; rr++)
        #pragma unroll
        for (int cc = 0; cc < 4; cc++)
            ob[(r0 + ty * 4 + rr) * C + tx + 32 * cc] = acc[rr][cc];

    // fused attention-coefficient epilogue (warp owns 4 full rows)
    float as[4], ad[4];
    #pragma unroll
    for (int cc = 0; cc < 4; cc++) {
        int col = tx + 32 * cc;
        int ai  = (HEADS == 4) ? (cc * 32 + tx) : col;  // identical, kept explicit
        as[cc] = asrc[ai];
        ad[cc] = adst[ai];
    }
    #pragma unroll
    for (int rr = 0; rr < 4; rr++) {
        int row = r0 + ty * 4 + rr;
        if (HEADS == 4) {
            #pragma unroll
            for (int cc = 0; cc < 4; cc++) {
                float ps = acc[rr][cc] * as[cc];
                float pd = acc[rr][cc] * ad[cc];
                #pragma unroll
                for (int off = 16; off > 0; off >>= 1) {
                    ps += __shfl_xor_sync(0xffffffffu, ps, off);
                    pd += __shfl_xor_sync(0xffffffffu, pd, off);
                }
                if (tx == 0) {
                    g_esrc[(gg * L + row) * 4 + cc] = ps;
                    g_edst[(gg * L + row) * 4 + cc] = pd;
                }
            }
        } else {
            float ps = 0.f, pd = 0.f;
            #pragma unroll
            for (int cc = 0; cc < 4; cc++) {
                ps += acc[rr][cc] * as[cc];
                pd += acc[rr][cc] * ad[cc];
            }
            #pragma unroll
            for (int off = 16; off > 0; off >>= 1) {
                ps += __shfl_xor_sync(0xffffffffu, ps, off);
                pd += __shfl_xor_sync(0xffffffffu, pd, off);
            }
            if (tx == 0) {
                g_esrc[(gg * L + row)] = ps;
                g_edst[(gg * L + row)] = pd;
            }
        }
    }
}

// ---------------- fused masked-softmax attention ----------------
// No phase-B: softmax shift m = leaky(s + max_all_j t) (valid upper bound, leaky
// is monotonic); unnormalized accumulation, normalize by 1/l in the epilogue.
// MODE 0: ELU -> g_h1.   MODE 1: residual + LayerNorm -> out.
template<int HEADS, int MODE>
__global__ void __launch_bounds__(128) k_attn(const float* __restrict__ feats,
                                              const float* __restrict__ gamma,
                                              const float* __restrict__ beta,
                                              float* __restrict__ out) {
    constexpr int TI = 32, JC = 16, HT = HEADS * TI;
    __shared__ float t_sh[L * HEADS];
    __shared__ __align__(16) float4 wf_sh[JC][32];
    __shared__ __align__(16) float alpha_sh[JC * HT];
    __shared__ uint32_t adj_tr[32][TI];               // [word][row] (transposed)
    __shared__ float s_sh[HT];
    __shared__ float l_sh[HT];
    __shared__ float pm[128];
    __shared__ float tm_sh[HEADS];

    int tid  = threadIdx.x;
    int lane = tid & 31, ig = tid >> 5;               // warp id 0..3, 8 rows each
    int dcol = lane;
    int gg   = blockIdx.x >> 5;
    int i0   = (blockIdx.x & 31) * TI;

    // load t (e_dst for all j) + per-thread partial max per head
    {
        float mp = -1e30f;
        const float* tg = g_edst + gg * L * HEADS;
        for (int idx = tid; idx < L * HEADS; idx += 128) {
            float v = tg[idx];
            t_sh[idx] = v;
            mp = fmaxf(mp, v);          // idx % HEADS == tid % HEADS (128 % 4 == 0)
        }
        pm[tid] = mp;
    }
    // adjacency tile, transposed for conflict-free per-row reads
    for (int idx = tid; idx < 32 * TI; idx += 128) {
        int w = idx >> 5, r = idx & 31;
        adj_tr[w][r] = g_adj[gg][i0 + r][w];
    }
    if (tid < HT) {
        s_sh[tid] = g_esrc[(gg * L + i0) * HEADS + tid];
        l_sh[tid] = 0.f;
    }
    __syncthreads();
    if (tid < HEADS) {
        float M = -1e30f;
        for (int k = tid; k < 128; k += HEADS) M = fmaxf(M, pm[k]);
        tm_sh[tid] = M;
    }
    __syncthreads();

    // per-thread alpha-generation constants
    const int nsub = 128 / HT;
    const int pair = tid & (HT - 1);
    const int sub  = tid / HT;
    const int ph   = pair / TI, pr = pair & (TI - 1);
    const float s  = s_sh[pr * HEADS + ph];
    const float m  = fmaxf(s + tm_sh[ph], NEG * (s + tm_sh[ph]));   // leaky(s+Tmax)
    float lacc = 0.f;

    constexpr int DH = 32 / HEADS;
    const int myh = dcol / DH;
    unsigned long long acc[16];                        // 8 rows x 2 f32x2 pairs
    #pragma unroll
    for (int k = 0; k < 16; k++) acc[k] = 0ULL;
    const float4* wfg = (const float4*)(g_wf + gg * L * C);

    for (int jb = 0; jb < L; jb += JC) {
        // Wf tile: 16 j x 32 f4
        #pragma unroll
        for (int it = 0; it < 4; it++) {
            int idx = tid + it * 128;
            wf_sh[idx >> 5][idx & 31] = wfg[(jb + (idx >> 5)) * 32 + (idx & 31)];
        }
        // alpha tile (unnormalized) + running row-sum
        {
            uint32_t wd = adj_tr[jb >> 5][pr];
            int bshift = jb & 16;
            #pragma unroll 4
            for (int jj = sub; jj < JC; jj += nsub) {
                float t = t_sh[(jb + jj) * HEADS + ph];
                float x = s + t;
                float e = fmaxf(x, NEG * x);
                float ev = __expf(e - m);
                float a = ((wd >> (bshift + jj)) & 1u) ? ev : 0.f;
                lacc += a;
                alpha_sh[jj * HT + pair] = a;
            }
        }
        __syncthreads();
        // acc += alpha * Wf  (packed f32x2 FMA)
        #pragma unroll 4
        for (int jj = 0; jj < JC; jj++) {
            ulonglong2 w = *(const ulonglong2*)&wf_sh[jj][dcol];
            const float4* ap = (const float4*)&alpha_sh[jj * HT + myh * TI + ig * 8];
            float4 a0 = ap[0], a1 = ap[1];
            float ar[8] = {a0.x, a0.y, a0.z, a0.w, a1.x, a1.y, a1.z, a1.w};
            #pragma unroll
            for (int r = 0; r < 8; r++) {
                unsigned long long d = dup2(ar[r]);
                ffma2(acc[2 * r],     d, w.x);
                ffma2(acc[2 * r + 1], d, w.y);
            }
        }
        __syncthreads();
    }

    // reduce l per (row,head)
    if (nsub == 1) l_sh[pair] = lacc;
    else atomicAdd(&l_sh[pair], lacc);
    __syncthreads();

    // epilogue
    #pragma unroll
    for (int rr = 0; rr < 8; rr++) {
        int rloc = ig * 8 + rr;
        int row  = i0 + rloc;
        float rl = 1.f / l_sh[myh * TI + rloc];
        float2 v0 = unpk(acc[2 * rr]), v1 = unpk(acc[2 * rr + 1]);
        float4 v = make_float4(v0.x * rl, v0.y * rl, v1.x * rl, v1.y * rl);
        if (MODE == 0) {
            v.x = v.x > 0.f ? v.x : expm1f(v.x);
            v.y = v.y > 0.f ? v.y : expm1f(v.y);
            v.z = v.z > 0.f ? v.z : expm1f(v.z);
            v.w = v.w > 0.f ? v.w : expm1f(v.w);
            ((float4*)(g_h1 + (gg * L + row) * C))[dcol] = v;
        } else {
            float4 y = ((const float4*)(feats + (gg * L + row) * C))[dcol];
            y.x += v.x; y.y += v.y; y.z += v.z; y.w += v.w;
            float sm = y.x + y.y + y.z + y.w;
            float sq = y.x * y.x + y.y * y.y + y.z * y.z + y.w * y.w;
            #pragma unroll
            for (int off = 16; off > 0; off >>= 1) {
                sm += __shfl_xor_sync(0xffffffffu, sm, off);
                sq += __shfl_xor_sync(0xffffffffu, sq, off);
            }
            float mean = sm * (1.f / 128.f);
            float var  = sq * (1.f / 128.f) - mean * mean;
            float inv  = rsqrtf(var + LNEPS);
            float4 gm = ((const float4*)gamma)[dcol];
            float4 bt = ((const float4*)beta)[dcol];
            float4 o;
            o.x = (y.x - mean) * inv * gm.x + bt.x;
            o.y = (y.y - mean) * inv * gm.y + bt.y;
            o.z = (y.z - mean) * inv * gm.z + bt.z;
            o.w = (y.w - mean) * inv * gm.w + bt.w;
            ((float4*)(out + (gg * L + row) * C))[dcol] = o;
        }
    }
}

// ---------------- launch ----------------
extern "C" void kernel_launch(void* const* d_in, const int* in_sizes, int n_in,
                              void* d_out, int out_size) {
    const float* seg_feats = (const float*)d_in[0];
    const int*   seg_img   = (const int*)d_in[1];
    const float* W1    = (const float*)d_in[3];
    const float* asrc1 = (const float*)d_in[4];
    const float* adst1 = (const float*)d_in[5];
    const float* W2    = (const float*)d_in[6];
    const float* asrc2 = (const float*)d_in[7];
    const float* adst2 = (const float*)d_in[8];
    const float* gamma = (const float*)d_in[9];
    const float* beta  = (const float*)d_in[10];
    float* out = (float*)d_out;

    k_adj_init <<<(BSG * L * 32 + 255) / 256, 256>>>();
    k_adj_build<<<(BSG * HIMG * WIMG + 255) / 256, 256>>>(seg_img);

    // layer 1
    k_gemm_nt<4><<<BSG * 32, 256>>>(seg_feats, W1, asrc1, adst1);
    k_attn<4, 0><<<BSG * 32, 128>>>(nullptr, nullptr, nullptr, nullptr);

    // layer 2 (input = g_h1 via in==nullptr)
    k_gemm_nt<1><<<BSG * 32, 256>>>(nullptr, W2, asrc2, adst2);
    k_attn<1, 1><<<BSG * 32, 128>>>(seg_feats, gamma, beta, out);
}

// round 3
// speedup vs baseline: 1.7351x; 1.1744x over previous
#include <cuda_runtime.h>
#include <math.h>
#include <stdint.h>

#define BSG   8          // B*S graphs
#define L     1024       // nodes per graph
#define C     128        // feature dim
#define HIMG  256
#define WIMG  256
#define NEG   0.2f
#define LNEPS 1e-5f

// ---------------- scratch (static device globals; no allocs) ----------------
__device__ uint32_t g_adj[BSG][L][L / 32];        // 1 MB adjacency bitmask
__device__ float    g_wf[BSG * L * C];            // Wf for current layer
__device__ float    g_h1[BSG * L * C];            // layer-1 output
__device__ float    g_esrc[BSG * L * 4];
__device__ float    g_edst[BSG * L * 4];

// ---------------- packed f32x2 helpers (FFMA2) ----------------
__device__ __forceinline__ unsigned long long dup2(float a) {
    unsigned long long r;
    asm("mov.b64 %0, {%1, %1};" : "=l"(r) : "f"(a));
    return r;
}
__device__ __forceinline__ void ffma2(unsigned long long& d,
                                      unsigned long long a, unsigned long long b) {
    asm("fma.rn.f32x2 %0, %1, %2, %0;" : "+l"(d) : "l"(a), "l"(b));
}
__device__ __forceinline__ float2 unpk(unsigned long long v) {
    float lo, hi;
    asm("mov.b64 {%0, %1}, %2;" : "=f"(lo), "=f"(hi) : "l"(v));
    return make_float2(lo, hi);
}

// ---------------- adjacency ----------------
__global__ void k_adj_init() {
    int idx = blockIdx.x * blockDim.x + threadIdx.x;   // BSG*L*32 words
    if (idx >= BSG * L * 32) return;
    int w = idx & 31;
    int i = (idx >> 5) & (L - 1);
    ((uint32_t*)g_adj)[idx] = (w == (i >> 5)) ? (1u << (i & 31)) : 0u;
}

__global__ void k_adj_build(const int* __restrict__ img) {
    int idx = blockIdx.x * blockDim.x + threadIdx.x;   // BSG*H*W pixels
    if (idx >= BSG * HIMG * WIMG) return;
    int x  = idx & (WIMG - 1);
    int y  = (idx >> 8) & (HIMG - 1);
    int gg = idx >> 16;
    const int* base = img + gg * HIMG * WIMG;
    int p = base[y * WIMG + x];

    auto edge = [&](int a, int b) {
        if (a > 0 && b > 0 && a != b) {
            int ai = a - 1, bi = b - 1;
            atomicOr(&g_adj[gg][ai][bi >> 5], 1u << (bi & 31));
            atomicOr(&g_adj[gg][bi][ai >> 5], 1u << (ai & 31));
        }
    };
    if (x + 1 < WIMG) edge(p, base[y * WIMG + x + 1]);
    if (y + 1 < HIMG) {
        edge(p, base[(y + 1) * WIMG + x]);
        if (x + 1 < WIMG) edge(p, base[(y + 1) * WIMG + x + 1]);
        if (x > 0)        edge(p, base[(y + 1) * WIMG + x - 1]);
    }
}

// ---------------- NT GEMM + fused e_src/e_dst epilogue ----------------
template<int HEADS>
__global__ void __launch_bounds__(256) k_gemm_nt(const float* __restrict__ in,
                                                 const float* __restrict__ W,
                                                 const float* __restrict__ asrc,
                                                 const float* __restrict__ adst) {
    __shared__ float4 xs[32][9];
    __shared__ float4 ws[128][9];
    int tid = threadIdx.x;
    int gg  = blockIdx.x >> 5;
    int r0  = (blockIdx.x & 31) * 32;
    const float* src = in ? (in + gg * L * C) : (g_h1 + gg * L * C);
    const float4* in4 = (const float4*)src;
    const float4* W4  = (const float4*)W;
    int tx = tid & 31, ty = tid >> 5;
    float acc[4][4] = {};

    for (int k0 = 0; k0 < 32; k0 += 8) {
        {
            int r = tid >> 3, kq = tid & 7;
            xs[r][kq] = in4[(r0 + r) * 32 + k0 + kq];
        }
        #pragma unroll
        for (int it = 0; it < 4; it++) {
            int idx = tid + it * 256;
            int o = idx >> 3, kq = idx & 7;
            ws[o][kq] = W4[o * 32 + k0 + kq];
        }
        __syncthreads();
        #pragma unroll
        for (int kq = 0; kq < 8; kq++) {
            float4 xv[4], wv[4];
            #pragma unroll
            for (int rr = 0; rr < 4; rr++) xv[rr] = xs[ty * 4 + rr][kq];
            #pragma unroll
            for (int cc = 0; cc < 4; cc++) wv[cc] = ws[tx + 32 * cc][kq];
            #pragma unroll
            for (int rr = 0; rr < 4; rr++)
                #pragma unroll
                for (int cc = 0; cc < 4; cc++)
                    acc[rr][cc] += xv[rr].x * wv[cc].x + xv[rr].y * wv[cc].y
                                 + xv[rr].z * wv[cc].z + xv[rr].w * wv[cc].w;
        }
        __syncthreads();
    }
    float* ob = g_wf + gg * L * C;
    #pragma unroll
    for (int rr = 0; rr < 4; rr++)
        #pragma unroll
        for (int cc = 0; cc < 4; cc++)
            ob[(r0 + ty * 4 + rr) * C + tx + 32 * cc] = acc[rr][cc];

    // fused attention-coefficient epilogue (warp owns 4 full rows)
    float as[4], ad[4];
    #pragma unroll
    for (int cc = 0; cc < 4; cc++) {
        int col = tx + 32 * cc;
        as[cc] = asrc[col];
        ad[cc] = adst[col];
    }
    #pragma unroll
    for (int rr = 0; rr < 4; rr++) {
        int row = r0 + ty * 4 + rr;
        if (HEADS == 4) {
            #pragma unroll
            for (int cc = 0; cc < 4; cc++) {
                float ps = acc[rr][cc] * as[cc];
                float pd = acc[rr][cc] * ad[cc];
                #pragma unroll
                for (int off = 16; off > 0; off >>= 1) {
                    ps += __shfl_xor_sync(0xffffffffu, ps, off);
                    pd += __shfl_xor_sync(0xffffffffu, pd, off);
                }
                if (tx == 0) {
                    g_esrc[(gg * L + row) * 4 + cc] = ps;
                    g_edst[(gg * L + row) * 4 + cc] = pd;
                }
            }
        } else {
            float ps = 0.f, pd = 0.f;
            #pragma unroll
            for (int cc = 0; cc < 4; cc++) {
                ps += acc[rr][cc] * as[cc];
                pd += acc[rr][cc] * ad[cc];
            }
            #pragma unroll
            for (int off = 16; off > 0; off >>= 1) {
                ps += __shfl_xor_sync(0xffffffffu, ps, off);
                pd += __shfl_xor_sync(0xffffffffu, pd, off);
            }
            if (tx == 0) {
                g_esrc[(gg * L + row)] = ps;
                g_edst[(gg * L + row)] = pd;
            }
        }
    }
}

// ---------------- fused masked-softmax attention ----------------
// Softmax shift m = leaky(s + max_all_j t) (valid upper bound; leaky monotonic).
// Unnormalized accumulation; normalize by 1/l in the epilogue.
// 256 threads, 8 warps, TI=32 rows/block, 4 rows per warp.
// MODE 0: ELU -> g_h1.   MODE 1: residual + LayerNorm -> out.
template<int HEADS, int MODE>
__global__ void __launch_bounds__(256) k_attn(const float* __restrict__ feats,
                                              const float* __restrict__ gamma,
                                              const float* __restrict__ beta,
                                              float* __restrict__ out) {
    constexpr int TI = 32, JC = 16, HT = HEADS * TI;
    __shared__ float t_sh[L * HEADS];
    __shared__ __align__(16) float4 wf_sh[JC][32];
    __shared__ __align__(16) float alpha_sh[JC * HT];
    __shared__ uint32_t adj_tr[32][TI];               // [word][row] transposed
    __shared__ float s_sh[HT];
    __shared__ float l_sh[HT];
    __shared__ float pm[256];
    __shared__ float tm_sh[HEADS];

    int tid  = threadIdx.x;
    int lane = tid & 31, ig = tid >> 5;               // warp 0..7, 4 rows each
    int dcol = lane;
    int gg   = blockIdx.x >> 5;
    int i0   = (blockIdx.x & 31) * TI;

    // load t (e_dst for all j) + per-thread partial max per head
    {
        float mp = -1e30f;
        const float* tg = g_edst + gg * L * HEADS;
        for (int idx = tid; idx < L * HEADS; idx += 256) {
            float v = tg[idx];
            t_sh[idx] = v;
            mp = fmaxf(mp, v);          // idx % HEADS == tid % HEADS (256 % 4 == 0)
        }
        pm[tid] = mp;
    }
    for (int idx = tid; idx < 32 * TI; idx += 256) {
        int w = idx >> 5, r = idx & 31;
        adj_tr[w][r] = g_adj[gg][i0 + r][w];
    }
    if (tid < HT) {
        s_sh[tid] = g_esrc[(gg * L + i0) * HEADS + tid];
        l_sh[tid] = 0.f;
    }
    __syncthreads();
    if (tid < HEADS) {
        float M = -1e30f;
        for (int k = tid; k < 256; k += HEADS) M = fmaxf(M, pm[k]);
        tm_sh[tid] = M;
    }
    __syncthreads();

    // per-thread alpha-generation constants
    constexpr int NSUB = 256 / HT;                    // 2 (H4) or 8 (H1)
    const int pair = tid & (HT - 1);
    const int sub  = tid / HT;
    const int ph   = pair / TI, pr = pair & (TI - 1);
    const float s  = s_sh[pr * HEADS + ph];
    const float m  = fmaxf(s + tm_sh[ph], NEG * (s + tm_sh[ph]));
    float lacc = 0.f;

    constexpr int DH = 32 / HEADS;
    const int myh = dcol / DH;
    unsigned long long acc[8];                        // 4 rows x 2 f32x2 pairs
    #pragma unroll
    for (int k = 0; k < 8; k++) acc[k] = 0ULL;
    const float4* wfg = (const float4*)(g_wf + gg * L * C);

    for (int jb = 0; jb < L; jb += JC) {
        // Wf tile: 16 j x 32 f4
        #pragma unroll
        for (int it = 0; it < 2; it++) {
            int idx = tid + it * 256;
            wf_sh[idx >> 5][idx & 31] = wfg[(jb + (idx >> 5)) * 32 + (idx & 31)];
        }
        // alpha tile (unnormalized) + running row-sum
        {
            uint32_t wd = adj_tr[jb >> 5][pr];
            int bshift = jb & 16;
            #pragma unroll
            for (int jj = sub; jj < JC; jj += NSUB) {
                float t = t_sh[(jb + jj) * HEADS + ph];
                float x = s + t;
                float e = fmaxf(x, NEG * x);
                float ev = __expf(e - m);
                float a = ((wd >> (bshift + jj)) & 1u) ? ev : 0.f;
                lacc += a;
                alpha_sh[jj * HT + pair] = a;
            }
        }
        __syncthreads();
        // acc += alpha * Wf  (packed f32x2 FMA), 4 rows per warp
        #pragma unroll
        for (int jj = 0; jj < JC; jj++) {
            ulonglong2 w = *(const ulonglong2*)&wf_sh[jj][dcol];
            float4 a0 = *(const float4*)&alpha_sh[jj * HT + myh * TI + ig * 4];
            float ar[4] = {a0.x, a0.y, a0.z, a0.w};
            #pragma unroll
            for (int r = 0; r < 4; r++) {
                unsigned long long d = dup2(ar[r]);
                ffma2(acc[2 * r],     d, w.x);
                ffma2(acc[2 * r + 1], d, w.y);
            }
        }
        __syncthreads();
    }

    // reduce l per (row,head)
    if (NSUB == 1) l_sh[pair] = lacc;
    else atomicAdd(&l_sh[pair], lacc);
    __syncthreads();

    // epilogue: warp ig owns rows ig*4 .. ig*4+3
    #pragma unroll
    for (int rr = 0; rr < 4; rr++) {
        int rloc = ig * 4 + rr;
        int row  = i0 + rloc;
        float rl = 1.f / l_sh[myh * TI + rloc];
        float2 v0 = unpk(acc[2 * rr]), v1 = unpk(acc[2 * rr + 1]);
        float4 v = make_float4(v0.x * rl, v0.y * rl, v1.x * rl, v1.y * rl);
        if (MODE == 0) {
            v.x = v.x > 0.f ? v.x : expm1f(v.x);
            v.y = v.y > 0.f ? v.y : expm1f(v.y);
            v.z = v.z > 0.f ? v.z : expm1f(v.z);
            v.w = v.w > 0.f ? v.w : expm1f(v.w);
            ((float4*)(g_h1 + (gg * L + row) * C))[dcol] = v;
        } else {
            float4 y = ((const float4*)(feats + (gg * L + row) * C))[dcol];
            y.x += v.x; y.y += v.y; y.z += v.z; y.w += v.w;
            float sm = y.x + y.y + y.z + y.w;
            float sq = y.x * y.x + y.y * y.y + y.z * y.z + y.w * y.w;
            #pragma unroll
            for (int off = 16; off > 0; off >>= 1) {
                sm += __shfl_xor_sync(0xffffffffu, sm, off);
                sq += __shfl_xor_sync(0xffffffffu, sq, off);
            }
            float mean = sm * (1.f / 128.f);
            float var  = sq * (1.f / 128.f) - mean * mean;
            float inv  = rsqrtf(var + LNEPS);
            float4 gm = ((const float4*)gamma)[dcol];
            float4 bt = ((const float4*)beta)[dcol];
            float4 o;
            o.x = (y.x - mean) * inv * gm.x + bt.x;
            o.y = (y.y - mean) * inv * gm.y + bt.y;
            o.z = (y.z - mean) * inv * gm.z + bt.z;
            o.w = (y.w - mean) * inv * gm.w + bt.w;
            ((float4*)(out + (gg * L + row) * C))[dcol] = o;
        }
    }
}

// ---------------- launch ----------------
extern "C" void kernel_launch(void* const* d_in, const int* in_sizes, int n_in,
                              void* d_out, int out_size) {
    const float* seg_feats = (const float*)d_in[0];
    const int*   seg_img   = (const int*)d_in[1];
    const float* W1    = (const float*)d_in[3];
    const float* asrc1 = (const float*)d_in[4];
    const float* adst1 = (const float*)d_in[5];
    const float* W2    = (const float*)d_in[6];
    const float* asrc2 = (const float*)d_in[7];
    const float* adst2 = (const float*)d_in[8];
    const float* gamma = (const float*)d_in[9];
    const float* beta  = (const float*)d_in[10];
    float* out = (float*)d_out;

    k_adj_init <<<(BSG * L * 32 + 255) / 256, 256>>>();
    k_adj_build<<<(BSG * HIMG * WIMG + 255) / 256, 256>>>(seg_img);

    // layer 1
    k_gemm_nt<4><<<BSG * 32, 256>>>(seg_feats, W1, asrc1, adst1);
    k_attn<4, 0><<<BSG * 32, 256>>>(nullptr, nullptr, nullptr, nullptr);

    // layer 2 (input = g_h1 via in==nullptr)
    k_gemm_nt<1><<<BSG * 32, 256>>>(nullptr, W2, asrc2, adst2);
    k_attn<1, 1><<<BSG * 32, 256>>>(seg_feats, gamma, beta, out);
}

// round 5
// speedup vs baseline: 2.0983x; 1.2093x over previous
#include <cuda_runtime.h>
#include <math.h>
#include <stdint.h>

#define BSG   8          // B*S graphs
#define L     1024       // nodes per graph
#define C     128        // feature dim
#define HIMG  256
#define WIMG  256
#define NEG   0.2f
#define LNEPS 1e-5f
#define NS    4          // j-splits
#define JSPAN (L / NS)   // 256

// ---------------- scratch (static device globals; no allocs) ----------------
__device__ uint32_t g_adj[BSG][L][L / 32];        // 1 MB adjacency bitmask
__device__ float    g_wf[BSG * L * C];            // Wf for current layer
__device__ float    g_h1[BSG * L * C];            // layer-1 output
__device__ float    g_esrc[BSG * L * 4];
__device__ float    g_edst[BSG * L * 4];
__device__ float    g_pacc[NS * BSG * L * C];     // 16 MB partial accumulators
__device__ float    g_pl[NS * BSG * L * 4];       // partial softmax sums [row][head]
__device__ float    g_tmax[BSG * 4];              // per-(graph,head) max of e_dst

// ---------------- packed f32x2 helpers (FFMA2) ----------------
__device__ __forceinline__ unsigned long long dup2(float a) {
    unsigned long long r;
    asm("mov.b64 %0, {%1, %1};" : "=l"(r) : "f"(a));
    return r;
}
__device__ __forceinline__ void ffma2(unsigned long long& d,
                                      unsigned long long a, unsigned long long b) {
    asm("fma.rn.f32x2 %0, %1, %2, %0;" : "+l"(d) : "l"(a), "l"(b));
}
__device__ __forceinline__ float2 unpk(unsigned long long v) {
    float lo, hi;
    asm("mov.b64 {%0, %1}, %2;" : "=f"(lo), "=f"(hi) : "l"(v));
    return make_float2(lo, hi);
}

// ---------------- adjacency ----------------
__global__ void k_adj_init() {
    int idx = blockIdx.x * blockDim.x + threadIdx.x;
    if (idx >= BSG * L * 32) return;
    int w = idx & 31;
    int i = (idx >> 5) & (L - 1);
    ((uint32_t*)g_adj)[idx] = (w == (i >> 5)) ? (1u << (i & 31)) : 0u;
}

__global__ void k_adj_build(const int* __restrict__ img) {
    int idx = blockIdx.x * blockDim.x + threadIdx.x;
    if (idx >= BSG * HIMG * WIMG) return;
    int x  = idx & (WIMG - 1);
    int y  = (idx >> 8) & (HIMG - 1);
    int gg = idx >> 16;
    const int* base = img + gg * HIMG * WIMG;
    int p = base[y * WIMG + x];

    auto edge = [&](int a, int b) {
        if (a > 0 && b > 0 && a != b) {
            int ai = a - 1, bi = b - 1;
            atomicOr(&g_adj[gg][ai][bi >> 5], 1u << (bi & 31));
            atomicOr(&g_adj[gg][bi][ai >> 5], 1u << (ai & 31));
        }
    };
    if (x + 1 < WIMG) edge(p, base[y * WIMG + x + 1]);
    if (y + 1 < HIMG) {
        edge(p, base[(y + 1) * WIMG + x]);
        if (x + 1 < WIMG) edge(p, base[(y + 1) * WIMG + x + 1]);
        if (x > 0)        edge(p, base[(y + 1) * WIMG + x - 1]);
    }
}

// ---------------- NT GEMM + fused e_src/e_dst epilogue ----------------
template<int HEADS>
__global__ void __launch_bounds__(256) k_gemm_nt(const float* __restrict__ in,
                                                 const float* __restrict__ W,
                                                 const float* __restrict__ asrc,
                                                 const float* __restrict__ adst) {
    __shared__ float4 xs[32][9];
    __shared__ float4 ws[128][9];
    int tid = threadIdx.x;
    int gg  = blockIdx.x >> 5;
    int r0  = (blockIdx.x & 31) * 32;
    const float* src = in ? (in + gg * L * C) : (g_h1 + gg * L * C);
    const float4* in4 = (const float4*)src;
    const float4* W4  = (const float4*)W;
    int tx = tid & 31, ty = tid >> 5;
    float acc[4][4] = {};

    for (int k0 = 0; k0 < 32; k0 += 8) {
        {
            int r = tid >> 3, kq = tid & 7;
            xs[r][kq] = in4[(r0 + r) * 32 + k0 + kq];
        }
        #pragma unroll
        for (int it = 0; it < 4; it++) {
            int idx = tid + it * 256;
            int o = idx >> 3, kq = idx & 7;
            ws[o][kq] = W4[o * 32 + k0 + kq];
        }
        __syncthreads();
        #pragma unroll
        for (int kq = 0; kq < 8; kq++) {
            float4 xv[4], wv[4];
            #pragma unroll
            for (int rr = 0; rr < 4; rr++) xv[rr] = xs[ty * 4 + rr][kq];
            #pragma unroll
            for (int cc = 0; cc < 4; cc++) wv[cc] = ws[tx + 32 * cc][kq];
            #pragma unroll
            for (int rr = 0; rr < 4; rr++)
                #pragma unroll
                for (int cc = 0; cc < 4; cc++)
                    acc[rr][cc] += xv[rr].x * wv[cc].x + xv[rr].y * wv[cc].y
                                 + xv[rr].z * wv[cc].z + xv[rr].w * wv[cc].w;
        }
        __syncthreads();
    }
    float* ob = g_wf + gg * L * C;
    #pragma unroll
    for (int rr = 0; rr < 4; rr++)
        #pragma unroll
        for (int cc = 0; cc < 4; cc++)
            ob[(r0 + ty * 4 + rr) * C + tx + 32 * cc] = acc[rr][cc];

    float as[4], ad[4];
    #pragma unroll
    for (int cc = 0; cc < 4; cc++) {
        int col = tx + 32 * cc;
        as[cc] = asrc[col];
        ad[cc] = adst[col];
    }
    #pragma unroll
    for (int rr = 0; rr < 4; rr++) {
        int row = r0 + ty * 4 + rr;
        if (HEADS == 4) {
            #pragma unroll
            for (int cc = 0; cc < 4; cc++) {
                float ps = acc[rr][cc] * as[cc];
                float pd = acc[rr][cc] * ad[cc];
                #pragma unroll
                for (int off = 16; off > 0; off >>= 1) {
                    ps += __shfl_xor_sync(0xffffffffu, ps, off);
                    pd += __shfl_xor_sync(0xffffffffu, pd, off);
                }
                if (tx == 0) {
                    g_esrc[(gg * L + row) * 4 + cc] = ps;
                    g_edst[(gg * L + row) * 4 + cc] = pd;
                }
            }
        } else {
            float ps = 0.f, pd = 0.f;
            #pragma unroll
            for (int cc = 0; cc < 4; cc++) {
                ps += acc[rr][cc] * as[cc];
                pd += acc[rr][cc] * ad[cc];
            }
            #pragma unroll
            for (int off = 16; off > 0; off >>= 1) {
                ps += __shfl_xor_sync(0xffffffffu, ps, off);
                pd += __shfl_xor_sync(0xffffffffu, pd, off);
            }
            if (tx == 0) {
                g_esrc[(gg * L + row)] = ps;
                g_edst[(gg * L + row)] = pd;
            }
        }
    }
}

// ---------------- per-(graph,head) max of e_dst ----------------
template<int HEADS>
__global__ void __launch_bounds__(256) k_tmax() {
    __shared__ float red[8];
    int gg = blockIdx.x / HEADS, h = blockIdx.x % HEADS;
    int tid = threadIdx.x;
    const float* tg = g_edst + gg * L * HEADS + h;
    float m = -1e30f;
    for (int j = tid; j < L; j += 256) m = fmaxf(m, tg[j * HEADS]);
    #pragma unroll
    for (int off = 16; off > 0; off >>= 1)
        m = fmaxf(m, __shfl_xor_sync(0xffffffffu, m, off));
    if ((tid & 31) == 0) red[tid >> 5] = m;
    __syncthreads();
    if (tid == 0) {
        #pragma unroll
        for (int k = 1; k < 8; k++) m = fmaxf(m, red[k]);
        g_tmax[gg * HEADS + h] = m;
    }
}

// ---------------- partial masked attention over one j-split ----------------
// Unnormalized partial acc + partial l; shift m = leaky(s + tmax) consistent
// across splits (valid upper bound since leaky is monotonic).
template<int HEADS>
__global__ void __launch_bounds__(256) k_attn_part() {
    constexpr int TI = 32, JC = 16, HT = HEADS * TI;
    __shared__ float t_sh[JSPAN * HEADS];
    __shared__ __align__(16) float4 wf_sh[JC][32];
    __shared__ __align__(16) float alpha_sh[JC * HT];
    __shared__ uint32_t adj_tr[JSPAN / 32][TI];
    __shared__ float s_sh[HT];                   // [row][head] (row-major)
    __shared__ float l_sh[HT];                   // [head][row] (pair layout!)

    int tid  = threadIdx.x;
    int lane = tid & 31, ig = tid >> 5;
    int dcol = lane;
    int b    = blockIdx.x;                       // BSG*32*NS blocks
    int js   = b & (NS - 1);
    int it   = (b >> 2) & 31;
    int gg   = b >> 7;
    int i0   = it * TI;
    int j0   = js * JSPAN;

    {
        const float* tg = g_edst + (gg * L + j0) * HEADS;
        for (int idx = tid; idx < JSPAN * HEADS; idx += 256) t_sh[idx] = tg[idx];
    }
    for (int idx = tid; idx < (JSPAN / 32) * TI; idx += 256) {
        int w = idx / TI, r = idx % TI;
        adj_tr[w][r] = g_adj[gg][i0 + r][(j0 >> 5) + w];
    }
    if (tid < HT) {
        s_sh[tid] = g_esrc[(gg * L + i0) * HEADS + tid];
        l_sh[tid] = 0.f;
    }
    __syncthreads();

    constexpr int NSUB = 256 / HT;               // 2 (H4), 8 (H1)
    const int pair = tid & (HT - 1);             // pair = ph*TI + pr
    const int sub  = tid / HT;
    const int ph   = pair / TI, pr = pair & (TI - 1);
    const float s  = s_sh[pr * HEADS + ph];
    const float sm0 = s + g_tmax[gg * HEADS + ph];
    const float m  = fmaxf(sm0, NEG * sm0);
    float lacc = 0.f;

    constexpr int DH = 32 / HEADS;
    const int myh = dcol / DH;
    unsigned long long acc[8];
    #pragma unroll
    for (int k = 0; k < 8; k++) acc[k] = 0ULL;
    const float4* wfg = (const float4*)(g_wf + (gg * L + j0) * C);

    for (int jb = 0; jb < JSPAN; jb += JC) {     // 16 iterations
        #pragma unroll
        for (int it2 = 0; it2 < 2; it2++) {
            int idx = tid + it2 * 256;
            wf_sh[idx >> 5][idx & 31] = wfg[(jb + (idx >> 5)) * 32 + (idx & 31)];
        }
        {
            uint32_t wd = adj_tr[jb >> 5][pr];
            int bshift = jb & 16;
            #pragma unroll
            for (int jj = sub; jj < JC; jj += NSUB) {
                float t = t_sh[(jb + jj) * HEADS + ph];
                float x = s + t;
                float e = fmaxf(x, NEG * x);
                float ev = __expf(e - m);
                float a = ((wd >> (bshift + jj)) & 1u) ? ev : 0.f;
                lacc += a;
                alpha_sh[jj * HT + pair] = a;
            }
        }
        __syncthreads();
        #pragma unroll
        for (int jj = 0; jj < JC; jj++) {
            ulonglong2 w = *(const ulonglong2*)&wf_sh[jj][dcol];
            float4 a0 = *(const float4*)&alpha_sh[jj * HT + myh * TI + ig * 4];
            float ar[4] = {a0.x, a0.y, a0.z, a0.w};
            #pragma unroll
            for (int r = 0; r < 4; r++) {
                unsigned long long d = dup2(ar[r]);
                ffma2(acc[2 * r],     d, w.x);
                ffma2(acc[2 * r + 1], d, w.y);
            }
        }
        __syncthreads();
    }

    if (NSUB == 1) l_sh[pair] = lacc;
    else atomicAdd(&l_sh[pair], lacc);
    __syncthreads();

    // write partials — NOTE l_sh is [head][row]; g_pl is [row][head]: transpose.
    if (tid < HT) {
        int r = tid / HEADS, h = tid % HEADS;
        g_pl[((js * BSG + gg) * L + i0 + r) * HEADS + h] = l_sh[h * TI + r];
    }
    float4* po = (float4*)(g_pacc + ((js * BSG + gg) * L) * C);
    #pragma unroll
    for (int rr = 0; rr < 4; rr++) {
        int rloc = ig * 4 + rr;
        float2 v0 = unpk(acc[2 * rr]), v1 = unpk(acc[2 * rr + 1]);
        po[(i0 + rloc) * 32 + dcol] = make_float4(v0.x, v0.y, v1.x, v1.y);
    }
}

// ---------------- combine partials + epilogue ----------------
// One warp per row (32 float4 lanes). MODE 0: ELU -> g_h1. MODE 1: LN -> out.
template<int HEADS, int MODE>
__global__ void __launch_bounds__(256) k_combine(const float* __restrict__ feats,
                                                 const float* __restrict__ gamma,
                                                 const float* __restrict__ beta,
                                                 float* __restrict__ out) {
    int gid  = blockIdx.x * 256 + threadIdx.x;   // BSG*L*32 threads
    int dcol = gid & 31;
    int row  = gid >> 5;                         // global row in [0, BSG*L)
    constexpr int DH = 32 / HEADS;
    int h = dcol / DH;

    float l = 0.f;
    float4 v = make_float4(0.f, 0.f, 0.f, 0.f);
    #pragma unroll
    for (int ns = 0; ns < NS; ns++) {
        l += g_pl[(ns * BSG * L + row) * HEADS + h];
        float4 p = ((const float4*)(g_pacc + ns * BSG * L * C))[row * 32 + dcol];
        v.x += p.x; v.y += p.y; v.z += p.z; v.w += p.w;
    }
    float rl = 1.f / l;
    v.x *= rl; v.y *= rl; v.z *= rl; v.w *= rl;

    if (MODE == 0) {
        v.x = v.x > 0.f ? v.x : expm1f(v.x);
        v.y = v.y > 0.f ? v.y : expm1f(v.y);
        v.z = v.z > 0.f ? v.z : expm1f(v.z);
        v.w = v.w > 0.f ? v.w : expm1f(v.w);
        ((float4*)g_h1)[row * 32 + dcol] = v;
    } else {
        float4 y = ((const float4*)feats)[row * 32 + dcol];
        y.x += v.x; y.y += v.y; y.z += v.z; y.w += v.w;
        float sm = y.x + y.y + y.z + y.w;
        float sq = y.x * y.x + y.y * y.y + y.z * y.z + y.w * y.w;
        #pragma unroll
        for (int off = 16; off > 0; off >>= 1) {
            sm += __shfl_xor_sync(0xffffffffu, sm, off);
            sq += __shfl_xor_sync(0xffffffffu, sq, off);
        }
        float mean = sm * (1.f / 128.f);
        float var  = sq * (1.f / 128.f) - mean * mean;
        float inv  = rsqrtf(var + LNEPS);
        float4 gm = ((const float4*)gamma)[dcol];
        float4 bt = ((const float4*)beta)[dcol];
        float4 o;
        o.x = (y.x - mean) * inv * gm.x + bt.x;
        o.y = (y.y - mean) * inv * gm.y + bt.y;
        o.z = (y.z - mean) * inv * gm.z + bt.z;
        o.w = (y.w - mean) * inv * gm.w + bt.w;
        ((float4*)out)[row * 32 + dcol] = o;
    }
}

// ---------------- launch ----------------
extern "C" void kernel_launch(void* const* d_in, const int* in_sizes, int n_in,
                              void* d_out, int out_size) {
    const float* seg_feats = (const float*)d_in[0];
    const int*   seg_img   = (const int*)d_in[1];
    const float* W1    = (const float*)d_in[3];
    const float* asrc1 = (const float*)d_in[4];
    const float* adst1 = (const float*)d_in[5];
    const float* W2    = (const float*)d_in[6];
    const float* asrc2 = (const float*)d_in[7];
    const float* adst2 = (const float*)d_in[8];
    const float* gamma = (const float*)d_in[9];
    const float* beta  = (const float*)d_in[10];
    float* out = (float*)d_out;

    k_adj_init <<<(BSG * L * 32 + 255) / 256, 256>>>();
    k_adj_build<<<(BSG * HIMG * WIMG + 255) / 256, 256>>>(seg_img);

    // layer 1
    k_gemm_nt<4><<<BSG * 32, 256>>>(seg_feats, W1, asrc1, adst1);
    k_tmax<4><<<BSG * 4, 256>>>();
    k_attn_part<4><<<BSG * 32 * NS, 256>>>();
    k_combine<4, 0><<<BSG * L * 32 / 256, 256>>>(nullptr, nullptr, nullptr, nullptr);

    // layer 2 (input = g_h1 via in==nullptr)
    k_gemm_nt<1><<<BSG * 32, 256>>>(nullptr, W2, asrc2, adst2);
    k_tmax<1><<<BSG * 1, 256>>>();
    k_attn_part<1><<<BSG * 32 * NS, 256>>>();
    k_combine<1, 1><<<BSG * L * 32 / 256, 256>>>(seg_feats, gamma, beta, out);
}